// round 6
// baseline (speedup 1.0000x reference)
#include <cuda_runtime.h>
#include <cuda_bf16.h>

// FactoredQuantizer: B=8192, M=16, N=256, C=64
//   inputs   [B, M, C] f32
//   codebook [M, N, C] f32
//   out: codes [B, M, C] f32  (+ idx [B, M] as f32 if out_size covers it)
//
// Round 4 -> 5 change: 2 queries per thread (128-thread blocks) so every
// broadcast LDS.128 of the code row feeds 2x the FFMA2 work. L1/shared was
// the 79% limiter; this halves LDS wavefronts per FLOP.

#define BQ 8192
#define MQ 16
#define NQ 256
#define CQ 64

typedef unsigned long long u64;

__device__ __forceinline__ u64 ffma2(u64 a, u64 b, u64 c) {
    u64 d;
    asm("fma.rn.f32x2 %0, %1, %2, %3;" : "=l"(d) : "l"(a), "l"(b), "l"(c));
    return d;
}
__device__ __forceinline__ u64 fadd2(u64 a, u64 b) {
    u64 d;
    asm("add.rn.f32x2 %0, %1, %2;" : "=l"(d) : "l"(a), "l"(b));
    return d;
}
__device__ __forceinline__ float sum2(u64 s) {
    float lo = __uint_as_float((unsigned)s);
    float hi = __uint_as_float((unsigned)(s >> 32));
    return lo + hi;
}

__global__ __launch_bounds__(128, 2)
void fq_kernel(const float* __restrict__ x,
               const float* __restrict__ cb,
               float* __restrict__ out_codes,
               float* __restrict__ out_idx) {
    extern __shared__ float smem[];           // [NQ*CQ] codebook + [NQ] c2
    float* s_cb = smem;
    float* s_c2 = smem + NQ * CQ;

    const int m = blockIdx.y;
    const int t = threadIdx.x;                // 0..127

    // ---- Stage codebook[m] (256x64 f32 = 64 KB) into shared, coalesced ----
    {
        const float4* g  = reinterpret_cast<const float4*>(cb + (size_t)m * NQ * CQ);
        float4*       s4 = reinterpret_cast<float4*>(s_cb);
        #pragma unroll
        for (int i = 0; i < 32; i++)
            s4[t + 128 * i] = g[t + 128 * i];
    }
    __syncthreads();

    // ---- c2[n] = ||c_n||^2 (each thread: 2 rows) ----
    #pragma unroll
    for (int r = 0; r < 2; r++) {
        int n = t + 128 * r;
        float s = 0.f;
        const float* row = s_cb + n * CQ;
        #pragma unroll
        for (int k = 0; k < CQ; k++) s = fmaf(row[k], row[k], s);
        s_c2[n] = s;
    }
    __syncthreads();

    // ---- Each thread owns TWO queries: b0 = base+t, b1 = base+t+128 ----
    const int b0 = blockIdx.x * 256 + t;
    const int b1 = b0 + 128;

    u64 xa[32], xb[32];
    {
        const ulonglong2* xg0 =
            reinterpret_cast<const ulonglong2*>(x + ((size_t)b0 * MQ + m) * CQ);
        const ulonglong2* xg1 =
            reinterpret_cast<const ulonglong2*>(x + ((size_t)b1 * MQ + m) * CQ);
        #pragma unroll
        for (int j = 0; j < 16; j++) {
            ulonglong2 v0 = xg0[j];
            xa[2 * j] = v0.x;  xa[2 * j + 1] = v0.y;
            ulonglong2 v1 = xg1[j];
            xb[2 * j] = v1.x;  xb[2 * j + 1] = v1.y;
        }
    }

    // ---- Main loop: per code, 16 LDS.128 feed 64 FFMA2 (2 queries) ----
    float best0 = 3.402823466e38f, best1 = 3.402823466e38f;
    int   idx0 = 0, idx1 = 0;
    const ulonglong2* cbase = reinterpret_cast<const ulonglong2*>(s_cb);
    for (int n = 0; n < NQ; n++) {
        const ulonglong2* crow = cbase + n * (CQ / 4);
        u64 p0 = 0ull, p1 = 0ull, p2 = 0ull, p3 = 0ull;  // query 0 accums
        u64 q0 = 0ull, q1 = 0ull, q2 = 0ull, q3 = 0ull;  // query 1 accums
        #pragma unroll
        for (int j = 0; j < 8; j++) {
            ulonglong2 c0 = crow[2 * j];       // LDS.128, warp-broadcast
            ulonglong2 c1 = crow[2 * j + 1];
            p0 = ffma2(xa[4 * j + 0], c0.x, p0);
            q0 = ffma2(xb[4 * j + 0], c0.x, q0);
            p1 = ffma2(xa[4 * j + 1], c0.y, p1);
            q1 = ffma2(xb[4 * j + 1], c0.y, q1);
            p2 = ffma2(xa[4 * j + 2], c1.x, p2);
            q2 = ffma2(xb[4 * j + 2], c1.x, q2);
            p3 = ffma2(xa[4 * j + 3], c1.y, p3);
            q3 = ffma2(xb[4 * j + 3], c1.y, q3);
        }
        float c2n = s_c2[n];
        float dot0 = sum2(fadd2(fadd2(p0, p1), fadd2(p2, p3)));
        float dot1 = sum2(fadd2(fadd2(q0, q1), fadd2(q2, q3)));
        float d0 = fmaf(-2.0f, dot0, c2n);
        float d1 = fmaf(-2.0f, dot1, c2n);
        if (d0 < best0) { best0 = d0; idx0 = n; }  // strict <: first-index ties
        if (d1 < best1) { best1 = d1; idx1 = n; }
    }

    // ---- Gather winning code rows -> output ----
    {
        float4* oc0 = reinterpret_cast<float4*>(out_codes + ((size_t)b0 * MQ + m) * CQ);
        float4* oc1 = reinterpret_cast<float4*>(out_codes + ((size_t)b1 * MQ + m) * CQ);
        const float4* s0 = reinterpret_cast<const float4*>(s_cb + idx0 * CQ);
        const float4* s1 = reinterpret_cast<const float4*>(s_cb + idx1 * CQ);
        #pragma unroll
        for (int j = 0; j < 16; j++) { oc0[j] = s0[j]; oc1[j] = s1[j]; }
    }
    if (out_idx) {
        out_idx[(size_t)b0 * MQ + m] = (float)idx0;
        out_idx[(size_t)b1 * MQ + m] = (float)idx1;
    }
}

extern "C" void kernel_launch(void* const* d_in, const int* in_sizes, int n_in,
                              void* d_out, int out_size) {
    const float* x  = (const float*)d_in[0];
    const float* cb = (const float*)d_in[1];
    if (n_in >= 2 && in_sizes[0] == MQ * NQ * CQ) {
        const float* tmp = x; x = cb; cb = tmp;
    }

    float* out_codes = (float*)d_out;
    float* out_idx   = nullptr;
    const long long codes_elems = (long long)BQ * MQ * CQ;   // 8388608
    if ((long long)out_size >= codes_elems + (long long)BQ * MQ)
        out_idx = out_codes + codes_elems;

    const size_t smem_bytes = (NQ * CQ + NQ) * sizeof(float);  // 66560
    cudaFuncSetAttribute(fq_kernel, cudaFuncAttributeMaxDynamicSharedMemorySize,
                         (int)smem_bytes);

    dim3 grid(BQ / 256, MQ);
    fq_kernel<<<grid, 128, smem_bytes>>>(x, cb, out_codes, out_idx);
}

// round 9
// speedup vs baseline: 1.8883x; 1.8883x over previous
#include <cuda_runtime.h>
#include <cuda_bf16.h>
#include <cstdint>

// FactoredQuantizer: B=8192, M=16, N=256, C=64
// R8: register-tiled outer product. Warp = 8 queries x 256 codes.
// Each lane owns 8 code rows (distinct-data LDS.128, padded rows -> no bank
// conflicts); x rows are warp-broadcast. FFMA2 packs over k-pairs (exact fp32).

#define BQ 8192
#define MQ 16
#define NQ 256
#define CQ 64
#define QW 8              // queries per warp
#define NTHREADS 256      // 8 warps -> 64 queries per block
#define QB 64
#define CPAD 68           // padded row length in floats (272 B, 16B-aligned)

typedef unsigned long long u64;

__device__ __forceinline__ u64 ffma2(u64 a, u64 b, u64 c) {
    u64 d;
    asm("fma.rn.f32x2 %0, %1, %2, %3;" : "=l"(d) : "l"(a), "l"(b), "l"(c));
    return d;
}
__device__ __forceinline__ float sum2(u64 s) {
    float lo = __uint_as_float((unsigned)s);
    float hi = __uint_as_float((unsigned)(s >> 32));
    return lo + hi;
}

// smem: codebook padded [256][68] f32 | x [64][64] f32 | c2 [256] f32
#define SM_CB_BYTES (NQ * CPAD * 4)            // 69632
#define SM_X_OFF    SM_CB_BYTES
#define SM_X_BYTES  (QB * CQ * 4)              // 16384
#define SM_C2_OFF   (SM_X_OFF + SM_X_BYTES)
#define SM_TOTAL    (SM_C2_OFF + NQ * 4)       // 87040

__global__ __launch_bounds__(NTHREADS, 1)
void fq_kernel(const float* __restrict__ x,
               const float* __restrict__ cb,
               float* __restrict__ out_codes,
               float* __restrict__ out_idx) {
    extern __shared__ char smem[];
    float* s_cb = (float*)smem;                 // padded rows
    float* s_x  = (float*)(smem + SM_X_OFF);
    float* s_c2 = (float*)(smem + SM_C2_OFF);

    const int t    = threadIdx.x;
    const int wid  = t >> 5;
    const int lane = t & 31;
    const int m     = blockIdx.y;
    const int qbase = blockIdx.x * QB;

    // ---- stage codebook[m] into padded rows (coalesced gmem, OK STS) ----
    {
        const float4* g = (const float4*)(cb + (size_t)m * NQ * CQ);
        #pragma unroll
        for (int i = 0; i < 16; i++) {
            int idx = t + NTHREADS * i;         // 0..4095
            int n = idx >> 4, k4 = idx & 15;
            float4 v = g[idx];
            *(float4*)(s_cb + n * CPAD + k4 * 4) = v;
        }
    }
    // ---- stage x tile [64][64] ----
    {
        #pragma unroll
        for (int i = 0; i < 4; i++) {
            int idx = t + NTHREADS * i;         // 0..1023
            int q = idx >> 4, k4 = idx & 15;
            float4 v = *(const float4*)(x + ((size_t)(qbase + q) * MQ + m) * CQ + k4 * 4);
            *(float4*)(s_x + q * CQ + k4 * 4) = v;
        }
    }
    __syncthreads();

    // ---- c2[n] ----
    {
        float s = 0.f;
        const float* row = s_cb + t * CPAD;
        #pragma unroll
        for (int k = 0; k < CQ; k++) s = fmaf(row[k], row[k], s);
        s_c2[t] = s;
    }
    __syncthreads();

    // ---- main: warp wid owns queries qbase+8*wid..+7, lanes split codes ----
    const float* xw = s_x + (wid * QW) * CQ;    // warp's 8 query rows
    float best = 3.402823466e38f;
    int   bidx = 0;
    float bq[QW];
    int   bi[QW];
    #pragma unroll
    for (int q = 0; q < QW; q++) { bq[q] = 3.402823466e38f; bi[q] = 0; }

    #pragma unroll
    for (int g = 0; g < 2; g++) {
        // lane's 4 code rows this group: n = lane + 32*(4g+j)
        const char* crow[4];
        #pragma unroll
        for (int j = 0; j < 4; j++)
            crow[j] = (const char*)(s_cb + (lane + 32 * (4 * g + j)) * CPAD);

        u64 acc[QW][4];
        #pragma unroll
        for (int q = 0; q < QW; q++)
            #pragma unroll
            for (int j = 0; j < 4; j++) acc[q][j] = 0ull;

        #pragma unroll 4
        for (int ch = 0; ch < 16; ch++) {       // k0 = 4*ch
            ulonglong2 cv[4];
            #pragma unroll
            for (int j = 0; j < 4; j++)
                cv[j] = *(const ulonglong2*)(crow[j] + ch * 16);  // distinct rows
            #pragma unroll
            for (int q = 0; q < QW; q++) {
                ulonglong2 xv = *(const ulonglong2*)(xw + q * CQ + ch * 4); // bcast
                #pragma unroll
                for (int j = 0; j < 4; j++) {
                    acc[q][j] = ffma2(xv.x, cv[j].x, acc[q][j]);
                    acc[q][j] = ffma2(xv.y, cv[j].y, acc[q][j]);
                }
            }
        }
        // consume group: dist = c2[n] - 2*dot ; n ascending in j (tie->first)
        #pragma unroll
        for (int j = 0; j < 4; j++) {
            int n = lane + 32 * (4 * g + j);
            float c2n = s_c2[n];
            #pragma unroll
            for (int q = 0; q < QW; q++) {
                float d = fmaf(-2.0f, sum2(acc[q][j]), c2n);
                if (d < bq[q]) { bq[q] = d; bi[q] = n; }
            }
        }
    }

    // ---- cross-lane argmin reduce per query (tie -> lower n) ----
    #pragma unroll
    for (int q = 0; q < QW; q++) {
        float v = bq[q]; int i = bi[q];
        #pragma unroll
        for (int o = 16; o > 0; o >>= 1) {
            float v2 = __shfl_xor_sync(0xffffffff, v, o);
            int   i2 = __shfl_xor_sync(0xffffffff, i, o);
            if (v2 < v || (v2 == v && i2 < i)) { v = v2; i = i2; }
        }
        bq[q] = v; bi[q] = i;
    }

    // ---- output: copy winning code rows (gmem codebook is L2-hot) ----
    #pragma unroll
    for (int q = 0; q < QW; q++) {
        int n = bi[q];
        int qq = wid * QW + q;
        size_t orow = ((size_t)(qbase + qq) * MQ + m) * CQ;
        const float2* src = (const float2*)(cb + ((size_t)m * NQ + n) * CQ);
        ((float2*)(out_codes + orow))[lane] = src[lane];
        if (lane == 0 && out_idx)
            out_idx[(size_t)(qbase + qq) * MQ + m] = (float)n;
    }
    (void)best; (void)bidx;
}

extern "C" void kernel_launch(void* const* d_in, const int* in_sizes, int n_in,
                              void* d_out, int out_size) {
    const float* x  = (const float*)d_in[0];
    const float* cb = (const float*)d_in[1];
    if (n_in >= 2 && in_sizes[0] == MQ * NQ * CQ) {
        const float* tmp = x; x = cb; cb = tmp;
    }

    float* out_codes = (float*)d_out;
    float* out_idx   = nullptr;
    const long long codes_elems = (long long)BQ * MQ * CQ;   // 8388608
    if ((long long)out_size >= codes_elems + (long long)BQ * MQ)
        out_idx = out_codes + codes_elems;

    cudaFuncSetAttribute(fq_kernel, cudaFuncAttributeMaxDynamicSharedMemorySize,
                         SM_TOTAL);
    dim3 grid(BQ / QB, MQ);
    fq_kernel<<<grid, NTHREADS, SM_TOTAL>>>(x, cb, out_codes, out_idx);
}

// round 10
// speedup vs baseline: 1.9392x; 1.0269x over previous
#include <cuda_runtime.h>
#include <cuda_bf16.h>
#include <cstdint>

// FactoredQuantizer: B=8192, M=16, N=256, C=64
// R9: register-tiled outer product, occupancy-balanced.
// Warp = 8 queries x 256 codes in 4 passes; each lane owns 2 code rows/pass
// (distinct-data LDS.128, padded rows -> conflict-free); x rows warp-broadcast.
// 16 u64 accumulators -> <=128 regs -> 2 blocks/SM (4 warps/SMSP).

#define BQ 8192
#define MQ 16
#define NQ 256
#define CQ 64
#define QW 8              // queries per warp
#define NTHREADS 256      // 8 warps -> 64 queries per block
#define QB 64
#define CPAD 68           // padded row length in floats (272 B, 16B-aligned)

typedef unsigned long long u64;

__device__ __forceinline__ u64 ffma2(u64 a, u64 b, u64 c) {
    u64 d;
    asm("fma.rn.f32x2 %0, %1, %2, %3;" : "=l"(d) : "l"(a), "l"(b), "l"(c));
    return d;
}
__device__ __forceinline__ float sum2(u64 s) {
    float lo = __uint_as_float((unsigned)s);
    float hi = __uint_as_float((unsigned)(s >> 32));
    return lo + hi;
}

// smem: codebook padded [256][68] f32 | x [64][64] f32 | c2 [256] f32
#define SM_CB_BYTES (NQ * CPAD * 4)            // 69632
#define SM_X_OFF    SM_CB_BYTES
#define SM_X_BYTES  (QB * CQ * 4)              // 16384
#define SM_C2_OFF   (SM_X_OFF + SM_X_BYTES)
#define SM_TOTAL    (SM_C2_OFF + NQ * 4)       // 87040

__global__ __launch_bounds__(NTHREADS, 2)
void fq_kernel(const float* __restrict__ x,
               const float* __restrict__ cb,
               float* __restrict__ out_codes,
               float* __restrict__ out_idx) {
    extern __shared__ char smem[];
    float* s_cb = (float*)smem;                 // padded rows
    float* s_x  = (float*)(smem + SM_X_OFF);
    float* s_c2 = (float*)(smem + SM_C2_OFF);

    const int t    = threadIdx.x;
    const int wid  = t >> 5;
    const int lane = t & 31;
    const int m     = blockIdx.y;
    const int qbase = blockIdx.x * QB;

    // ---- stage codebook[m] into padded rows (coalesced gmem reads) ----
    {
        const float4* g = (const float4*)(cb + (size_t)m * NQ * CQ);
        #pragma unroll
        for (int i = 0; i < 16; i++) {
            int idx = t + NTHREADS * i;         // 0..4095
            int n = idx >> 4, k4 = idx & 15;
            float4 v = g[idx];
            *(float4*)(s_cb + n * CPAD + k4 * 4) = v;
        }
    }
    // ---- stage x tile [64][64] ----
    {
        #pragma unroll
        for (int i = 0; i < 4; i++) {
            int idx = t + NTHREADS * i;         // 0..1023
            int q = idx >> 4, k4 = idx & 15;
            float4 v = *(const float4*)(x + ((size_t)(qbase + q) * MQ + m) * CQ + k4 * 4);
            *(float4*)(s_x + q * CQ + k4 * 4) = v;
        }
    }
    __syncthreads();

    // ---- c2[n] ----
    {
        float s = 0.f;
        const float* row = s_cb + t * CPAD;
        #pragma unroll
        for (int k = 0; k < CQ; k++) s = fmaf(row[k], row[k], s);
        s_c2[t] = s;
    }
    __syncthreads();

    // ---- main: warp wid owns queries qbase+8*wid..+7, lanes split codes ----
    const float* xw = s_x + (wid * QW) * CQ;    // warp's 8 query rows
    float bq[QW];
    int   bi[QW];
    #pragma unroll
    for (int q = 0; q < QW; q++) { bq[q] = 3.402823466e38f; bi[q] = 0; }

    #pragma unroll
    for (int p = 0; p < 4; p++) {
        // lane's 2 code rows this pass: n0 = lane + 64p, n1 = n0 + 32
        const int n0 = lane + 64 * p;
        const char* c0 = (const char*)(s_cb + n0 * CPAD);
        const char* c1 = (const char*)(s_cb + (n0 + 32) * CPAD);

        u64 acc[QW][2];
        #pragma unroll
        for (int q = 0; q < QW; q++) { acc[q][0] = 0ull; acc[q][1] = 0ull; }

        #pragma unroll 4
        for (int ch = 0; ch < 16; ch++) {       // k0 = 4*ch
            ulonglong2 cv0 = *(const ulonglong2*)(c0 + ch * 16);  // distinct rows
            ulonglong2 cv1 = *(const ulonglong2*)(c1 + ch * 16);
            #pragma unroll
            for (int q = 0; q < QW; q++) {
                ulonglong2 xv = *(const ulonglong2*)(xw + q * CQ + ch * 4); // bcast
                acc[q][0] = ffma2(xv.x, cv0.x, acc[q][0]);
                acc[q][0] = ffma2(xv.y, cv0.y, acc[q][0]);
                acc[q][1] = ffma2(xv.x, cv1.x, acc[q][1]);
                acc[q][1] = ffma2(xv.y, cv1.y, acc[q][1]);
            }
        }
        // consume pass: dist = c2[n] - 2*dot ; n ascending (tie -> first)
        float c20 = s_c2[n0];
        float c21 = s_c2[n0 + 32];
        #pragma unroll
        for (int q = 0; q < QW; q++) {
            float d0 = fmaf(-2.0f, sum2(acc[q][0]), c20);
            float d1 = fmaf(-2.0f, sum2(acc[q][1]), c21);
            if (d0 < bq[q]) { bq[q] = d0; bi[q] = n0; }
            if (d1 < bq[q]) { bq[q] = d1; bi[q] = n0 + 32; }
        }
    }

    // ---- cross-lane argmin reduce per query (tie -> lower n) ----
    #pragma unroll
    for (int q = 0; q < QW; q++) {
        float v = bq[q]; int i = bi[q];
        #pragma unroll
        for (int o = 16; o > 0; o >>= 1) {
            float v2 = __shfl_xor_sync(0xffffffff, v, o);
            int   i2 = __shfl_xor_sync(0xffffffff, i, o);
            if (v2 < v || (v2 == v && i2 < i)) { v = v2; i = i2; }
        }
        bi[q] = i;
    }

    // ---- output: copy winning code rows (gmem codebook is L2-hot) ----
    #pragma unroll
    for (int q = 0; q < QW; q++) {
        int n = bi[q];
        int qq = wid * QW + q;
        size_t orow = ((size_t)(qbase + qq) * MQ + m) * CQ;
        const float2* src = (const float2*)(cb + ((size_t)m * NQ + n) * CQ);
        ((float2*)(out_codes + orow))[lane] = src[lane];
        if (lane == 0 && out_idx)
            out_idx[(size_t)(qbase + qq) * MQ + m] = (float)n;
    }
}

extern "C" void kernel_launch(void* const* d_in, const int* in_sizes, int n_in,
                              void* d_out, int out_size) {
    const float* x  = (const float*)d_in[0];
    const float* cb = (const float*)d_in[1];
    if (n_in >= 2 && in_sizes[0] == MQ * NQ * CQ) {
        const float* tmp = x; x = cb; cb = tmp;
    }

    float* out_codes = (float*)d_out;
    float* out_idx   = nullptr;
    const long long codes_elems = (long long)BQ * MQ * CQ;   // 8388608
    if ((long long)out_size >= codes_elems + (long long)BQ * MQ)
        out_idx = out_codes + codes_elems;

    cudaFuncSetAttribute(fq_kernel, cudaFuncAttributeMaxDynamicSharedMemorySize,
                         SM_TOTAL);
    dim3 grid(BQ / QB, MQ);
    fq_kernel<<<grid, NTHREADS, SM_TOTAL>>>(x, cb, out_codes, out_idx);
}